// round 3
// baseline (speedup 1.0000x reference)
#include <cuda_runtime.h>
#include <cstdint>

// ---------------- problem constants ----------------
#define IN_F   4096
#define OUT_F  16384
#define NTOK   64
#define RANK   64

#define BLOCK_M 128          // out-features per CTA
#define KBLK    32           // K elems per pipeline stage
#define STAGES  4
#define NCHUNK_MAIN (IN_F / KBLK)            // 128
#define NCHUNK_TOT  (NCHUNK_MAIN + RANK/KBLK) // 130 (2 lora tail chunks)

#define PAD 36                                // floats per smem row (32 + 4 pad)
#define W_TILE_FLOATS (BLOCK_M * PAD)         // 4608
#define X_TILE_FLOATS (NTOK * PAD)            // 2304
#define STAGE_FLOATS  (W_TILE_FLOATS + X_TILE_FLOATS)   // 6912
#define SMEM_BYTES    (STAGE_FLOATS * STAGES * 4)       // 110592

// device scratch (static allocs are allowed)
__device__ __align__(256) float g_t2[NTOK * RANK];     // 2*(x@A^T), tf32-rounded
__device__ __align__(256) float g_xr[NTOK * IN_F];     // x, tf32-rounded

// ---------------- small PTX helpers ----------------
__device__ __forceinline__ uint32_t smem_u32(const void* p) {
    uint32_t a;
    asm("{ .reg .u64 t; cvta.to.shared.u64 t, %1; cvt.u32.u64 %0, t; }" : "=r"(a) : "l"(p));
    return a;
}
__device__ __forceinline__ uint32_t f2tf32(float f) {
    uint32_t r;
    asm("cvt.rna.tf32.f32 %0, %1;" : "=r"(r) : "f"(f));
    return r;
}
__device__ __forceinline__ void cp16(uint32_t dst, const float* src) {
    asm volatile("cp.async.cg.shared.global [%0], [%1], 16;" :: "r"(dst), "l"(src));
}
#define CP_COMMIT() asm volatile("cp.async.commit_group;" ::: "memory")
#define CP_WAIT2()  asm volatile("cp.async.wait_group 2;" ::: "memory")

__device__ __forceinline__ void mma_tf32(float* d,
                                         uint32_t a0, uint32_t a1, uint32_t a2, uint32_t a3,
                                         uint32_t b0, uint32_t b1) {
    asm volatile(
        "mma.sync.aligned.m16n8k8.row.col.f32.tf32.tf32.f32 "
        "{%0,%1,%2,%3}, {%4,%5,%6,%7}, {%8,%9}, {%0,%1,%2,%3};"
        : "+f"(d[0]), "+f"(d[1]), "+f"(d[2]), "+f"(d[3])
        : "r"(a0), "r"(a1), "r"(a2), "r"(a3), "r"(b0), "r"(b1));
}

// ---------------- prep 1: round x to tf32 ----------------
__global__ void __launch_bounds__(256) round_x_kernel(const float* __restrict__ x,
                                                      float* __restrict__ xr) {
    int i = blockIdx.x * 256 + threadIdx.x;
    xr[i] = __uint_as_float(f2tf32(x[i]));
}

// ---------------- prep 2: t2 = round_tf32( 2 * (x @ A^T) ) ----------------
// grid 64 = (8 token-groups x 8 r-groups), 256 threads
__global__ void __launch_bounds__(256) lora_t_kernel(const float* __restrict__ x,
                                                     const float* __restrict__ A,
                                                     float* __restrict__ t2) {
    __shared__ float red[256];
    int tid  = threadIdx.x;
    int pair = tid & 63;
    int i  = pair >> 3;           // local token 0..7
    int j  = pair & 7;            // local r 0..7
    int kg = tid >> 6;            // k-group 0..3
    int gi = (blockIdx.x >> 3) * 8 + i;
    int gj = (blockIdx.x & 7) * 8 + j;

    const float4* xr = (const float4*)(x + (size_t)gi * IN_F);
    const float4* ar = (const float4*)(A + (size_t)gj * IN_F);
    float acc = 0.f;
    int k0 = kg * 256;
#pragma unroll 4
    for (int k = k0; k < k0 + 256; ++k) {
        float4 a = xr[k];
        float4 b = ar[k];
        acc += a.x * b.x + a.y * b.y + a.z * b.z + a.w * b.w;
    }
    red[tid] = acc;
    __syncthreads();
    if (kg == 0) {
        float s = red[pair] + red[pair + 64] + red[pair + 128] + red[pair + 192];
        t2[gi * RANK + gj] = __uint_as_float(f2tf32(2.0f * s));
    }
}

// ---------------- main fused GEMM: mma.sync tf32, cp.async 4-stage ----------------
// grid = 128 CTAs, 256 threads (8 warps: 4 along M x 2 along N)
__global__ void __launch_bounds__(256, 1) lora_main_kernel(
    const float* __restrict__ x_r,     // pre-rounded x [64,4096]
    const float* __restrict__ w,       // [16384,4096]
    const float* __restrict__ lB,      // [16384,64]
    const float* __restrict__ t2,      // [64,64] pre-rounded (incl. 2x scale)
    float* __restrict__ out)           // [64,16384]
{
    extern __shared__ __align__(16) float smem[];
    const uint32_t sb = smem_u32(smem);
    const int tid  = threadIdx.x;
    const int wid  = tid >> 5;
    const int lane = tid & 31;
    const int g = lane >> 2;          // fragment group row
    const int t = lane & 3;           // fragment thread-in-group
    const int wm = (wid & 3) * 32;    // warp M offset in CTA tile
    const int wn = (wid >> 2) * 32;   // warp N offset (tokens)
    const int m_base = blockIdx.x * BLOCK_M;

    // ---- stage loader ----
    auto load_stage = [&](int chunk, int stage) {
        const float* a_base; int a_stride;
        const float* b_base; int b_stride;
        int k0;
        if (chunk < NCHUNK_MAIN) {
            a_base = w + (size_t)m_base * IN_F;  a_stride = IN_F;
            b_base = x_r;                        b_stride = IN_F;
            k0 = chunk * KBLK;
        } else {
            a_base = lB + (size_t)m_base * RANK; a_stride = RANK;
            b_base = t2;                         b_stride = RANK;
            k0 = (chunk - NCHUNK_MAIN) * KBLK;
        }
        uint32_t s_w = sb + (uint32_t)(stage * STAGE_FLOATS) * 4;
        uint32_t s_x = s_w + W_TILE_FLOATS * 4;
        // W tile: 128 rows x 8 chunks of 16B = 1024 ops / 256 thr = 4 each
#pragma unroll
        for (int i = 0; i < 4; ++i) {
            int idx = tid + i * 256;
            int row = idx >> 3, c = idx & 7;
            cp16(s_w + (uint32_t)(row * PAD + c * 4) * 4,
                 a_base + (size_t)row * a_stride + k0 + c * 4);
        }
        // x tile: 64 rows x 8 chunks = 512 ops / 256 thr = 2 each
#pragma unroll
        for (int i = 0; i < 2; ++i) {
            int idx = tid + i * 256;
            int row = idx >> 3, c = idx & 7;
            cp16(s_x + (uint32_t)(row * PAD + c * 4) * 4,
                 b_base + (size_t)row * b_stride + k0 + c * 4);
        }
    };

    // ---- prologue: stages 0..S-2 in flight ----
#pragma unroll
    for (int s = 0; s < STAGES - 1; ++s) {
        load_stage(s, s);
        CP_COMMIT();
    }

    float d[2][4][4];
#pragma unroll
    for (int mi = 0; mi < 2; ++mi)
#pragma unroll
        for (int ni = 0; ni < 4; ++ni)
#pragma unroll
            for (int r = 0; r < 4; ++r) d[mi][ni][r] = 0.f;

    // ---- mainloop ----
    for (int it = 0; it < NCHUNK_TOT; ++it) {
        CP_WAIT2();              // chunk `it` resident; <= S-2 groups pending
        __syncthreads();         // all warps done with stage (it-1)%S, see stage it
        {                        // refill: chunk it+S-1 -> stage (it+S-1)%S == (it-1)%S
            int nc = it + STAGES - 1;
            if (nc < NCHUNK_TOT) load_stage(nc, nc & (STAGES - 1));
            CP_COMMIT();         // commit even if empty: keeps group count uniform
        }
        const float* ws = smem + (it & (STAGES - 1)) * STAGE_FLOATS;
        const float* xs = ws + W_TILE_FLOATS;

#pragma unroll
        for (int k8 = 0; k8 < KBLK / 8; ++k8) {
            const int kk = k8 * 8;
            uint32_t a[2][4];
#pragma unroll
            for (int mi = 0; mi < 2; ++mi) {
                const float* wr = ws + (wm + mi * 16 + g) * PAD + kk + t;
                a[mi][0] = f2tf32(wr[0]);
                a[mi][1] = f2tf32(wr[8 * PAD]);
                a[mi][2] = f2tf32(wr[4]);
                a[mi][3] = f2tf32(wr[8 * PAD + 4]);
            }
            uint32_t b[4][2];
#pragma unroll
            for (int ni = 0; ni < 4; ++ni) {
                const float* xr = xs + (wn + ni * 8 + g) * PAD + kk + t;
                b[ni][0] = __float_as_uint(xr[0]);   // pre-rounded
                b[ni][1] = __float_as_uint(xr[4]);
            }
#pragma unroll
            for (int mi = 0; mi < 2; ++mi)
#pragma unroll
                for (int ni = 0; ni < 4; ++ni)
                    mma_tf32(d[mi][ni], a[mi][0], a[mi][1], a[mi][2], a[mi][3],
                             b[ni][0], b[ni][1]);
        }
        __syncthreads();         // stage consumed before producer may overwrite
    }

    // ---- epilogue: D[m][n] -> out[n][m] ----
#pragma unroll
    for (int mi = 0; mi < 2; ++mi) {
#pragma unroll
        for (int ni = 0; ni < 4; ++ni) {
            int m = m_base + wm + mi * 16 + g;
            int n = wn + ni * 8 + 2 * t;
            out[(size_t)n * OUT_F + m]           = d[mi][ni][0];
            out[(size_t)(n + 1) * OUT_F + m]     = d[mi][ni][1];
            out[(size_t)n * OUT_F + m + 8]       = d[mi][ni][2];
            out[(size_t)(n + 1) * OUT_F + m + 8] = d[mi][ni][3];
        }
    }
}

// ---------------- host launch ----------------
extern "C" void kernel_launch(void* const* d_in, const int* in_sizes, int n_in,
                              void* d_out, int out_size) {
    const float* x  = (const float*)d_in[0];   // [64, 4096]
    const float* w  = (const float*)d_in[1];   // [16384, 4096]
    const float* lA = (const float*)d_in[2];   // [64, 4096]
    const float* lB = (const float*)d_in[3];   // [16384, 64]
    float* out = (float*)d_out;                // [64, 16384]

    void* t2_ptr = nullptr;
    void* xr_ptr = nullptr;
    cudaGetSymbolAddress(&t2_ptr, g_t2);
    cudaGetSymbolAddress(&xr_ptr, g_xr);

    round_x_kernel<<<(NTOK * IN_F) / 256, 256>>>(x, (float*)xr_ptr);
    lora_t_kernel<<<64, 256>>>(x, lA, (float*)t2_ptr);

    static int smem_set = 0;
    if (!smem_set) {
        cudaFuncSetAttribute(lora_main_kernel,
                             cudaFuncAttributeMaxDynamicSharedMemorySize, SMEM_BYTES);
        smem_set = 1;
    }
    lora_main_kernel<<<OUT_F / BLOCK_M, 256, SMEM_BYTES>>>(
        (const float*)xr_ptr, w, lB, (const float*)t2_ptr, out);
}

// round 4
// speedup vs baseline: 1.1571x; 1.1571x over previous
#include <cuda_runtime.h>
#include <cuda_fp16.h>
#include <cstdint>

// ---------------- problem constants ----------------
#define IN_F   4096
#define OUT_F  16384
#define NTOK   64
#define RANK   64

#define BLOCK_M 128          // out-features per CTA
#define KBLK    32           // K elems per pipeline stage
#define STAGES  4
#define NCHUNK_MAIN (IN_F / KBLK)             // 128
#define NCHUNK_TOT  (NCHUNK_MAIN + RANK/KBLK) // 130

// ---------------- SMEM layout ----------------
// W32 staged fp32 tiles: 128 rows x (32+4 pad) floats
#define P32        36
#define W32_STAGE_F (BLOCK_M * P32)           // 4608 floats
#define W32_STAGE_B (W32_STAGE_F * 4)         // 18432 B
#define OFF_W32    0
// Wh: single converted fp16 tile, 128 rows x (32+8 pad) halfs
#define PH         40
#define OFF_WH     (STAGES * W32_STAGE_B)     // 73728
#define WH_BYTES   (BLOCK_M * PH * 2)         // 10240
// Xh staged fp16 tiles: 64 rows x 40 halfs
#define OFF_XH     (OFF_WH + WH_BYTES)        // 83968
#define XH_STAGE_B (NTOK * PH * 2)            // 5120
#define SMEM_BYTES (OFF_XH + STAGES * XH_STAGE_B)  // 104448

// device scratch
__device__ __align__(256) __half g_xh[NTOK * IN_F];   // x in fp16
__device__ __align__(256) __half g_t2h[NTOK * RANK];  // 2*(x@A^T) in fp16

// ---------------- PTX helpers ----------------
__device__ __forceinline__ uint32_t smem_u32(const void* p) {
    uint32_t a;
    asm("{ .reg .u64 t; cvta.to.shared.u64 t, %1; cvt.u32.u64 %0, t; }" : "=r"(a) : "l"(p));
    return a;
}
__device__ __forceinline__ void cp16(uint32_t dst, const void* src) {
    asm volatile("cp.async.cg.shared.global [%0], [%1], 16;" :: "r"(dst), "l"(src));
}
#define CP_COMMIT() asm volatile("cp.async.commit_group;" ::: "memory")
#define CP_WAIT2()  asm volatile("cp.async.wait_group 2;" ::: "memory")

__device__ __forceinline__ void ldsm4(uint32_t* r, uint32_t addr) {
    asm volatile("ldmatrix.sync.aligned.m8n8.x4.shared.b16 {%0,%1,%2,%3}, [%4];"
                 : "=r"(r[0]), "=r"(r[1]), "=r"(r[2]), "=r"(r[3]) : "r"(addr));
}
__device__ __forceinline__ void mma_f16(float* d, const uint32_t* a,
                                        uint32_t b0, uint32_t b1) {
    asm volatile(
        "mma.sync.aligned.m16n8k16.row.col.f32.f16.f16.f32 "
        "{%0,%1,%2,%3}, {%4,%5,%6,%7}, {%8,%9}, {%0,%1,%2,%3};"
        : "+f"(d[0]), "+f"(d[1]), "+f"(d[2]), "+f"(d[3])
        : "r"(a[0]), "r"(a[1]), "r"(a[2]), "r"(a[3]), "r"(b0), "r"(b1));
}
__device__ __forceinline__ uint32_t h2u(__half2 h) {
    return *reinterpret_cast<uint32_t*>(&h);
}

// ---------------- prep 1: x -> fp16 ----------------
__global__ void __launch_bounds__(256) x2h_kernel(const float4* __restrict__ x4,
                                                  uint2* __restrict__ xh2) {
    int i = blockIdx.x * 256 + threadIdx.x;
    float4 v = x4[i];
    uint2 o;
    o.x = h2u(__floats2half2_rn(v.x, v.y));
    o.y = h2u(__floats2half2_rn(v.z, v.w));
    xh2[i] = o;
}

// ---------------- prep 2: t2h = fp16( 2 * (x @ A^T) ) ----------------
__global__ void __launch_bounds__(256) lora_t_kernel(const float* __restrict__ x,
                                                     const float* __restrict__ A,
                                                     __half* __restrict__ t2) {
    __shared__ float red[256];
    int tid  = threadIdx.x;
    int pair = tid & 63;
    int i  = pair >> 3;
    int j  = pair & 7;
    int kg = tid >> 6;
    int gi = (blockIdx.x >> 3) * 8 + i;
    int gj = (blockIdx.x & 7) * 8 + j;

    const float4* xr = (const float4*)(x + (size_t)gi * IN_F);
    const float4* ar = (const float4*)(A + (size_t)gj * IN_F);
    float acc = 0.f;
    int k0 = kg * 256;
#pragma unroll 4
    for (int k = k0; k < k0 + 256; ++k) {
        float4 a = xr[k];
        float4 b = ar[k];
        acc += a.x * b.x + a.y * b.y + a.z * b.z + a.w * b.w;
    }
    red[tid] = acc;
    __syncthreads();
    if (kg == 0) {
        float s = red[pair] + red[pair + 64] + red[pair + 128] + red[pair + 192];
        t2[gi * RANK + gj] = __float2half_rn(2.0f * s);
    }
}

// ---------------- main fused GEMM: fp16 mma.m16n8k16, cp.async 4-stage ----------------
// 128 CTAs, 256 threads (8 warps: 4 along M x 2 along N). W converted fp32->fp16 in SMEM.
__global__ void __launch_bounds__(256, 1) lora_main_kernel(
    const __half* __restrict__ xh,     // [64,4096] fp16
    const float*  __restrict__ w,      // [16384,4096] fp32
    const float*  __restrict__ lB,     // [16384,64] fp32
    const __half* __restrict__ t2h,    // [64,64] fp16 (incl. 2x scale)
    float* __restrict__ out)           // [64,16384]
{
    extern __shared__ __align__(16) char smem_c[];
    float* smem_f = (float*)smem_c;
    const uint32_t sb = smem_u32(smem_c);
    const int tid  = threadIdx.x;
    const int wid  = tid >> 5;
    const int lane = tid & 31;
    const int g = lane >> 2;
    const int t = lane & 3;
    const int wm = (wid & 3) * 32;    // warp M offset
    const int wn = (wid >> 2) * 32;   // warp N offset (tokens)
    const int m_base = blockIdx.x * BLOCK_M;

    // ---- per-lane ldmatrix row offsets (bytes) ----
    // A (Wh): matrices [m0-7/k0, m8-15/k0, m0-7/k8, m8-15/k8]
    const int a_row  = (lane & 7) + ((lane >> 3) & 1) * 8;
    const uint32_t a_byte = ((lane >> 4) & 1) * 16;
    const uint32_t wh_base = sb + OFF_WH;
    const uint32_t a_off0 = wh_base + (uint32_t)(wm + a_row) * (PH * 2) + a_byte;
    const uint32_t a_off1 = a_off0 + 16 * (PH * 2);
    // B (Xh): matrices [n0-7/k0, n0-7/k8, n8-15/k0, n8-15/k8]
    const int b_row  = (lane & 7) + ((lane >> 4) & 1) * 8;
    const uint32_t b_byte = ((lane >> 3) & 1) * 16;
    const uint32_t b_off0 = (uint32_t)(wn + b_row) * (PH * 2) + b_byte;
    const uint32_t b_off1 = b_off0 + 16 * (PH * 2);

    // ---- stage loader: cp.async W fp32 tile + Xh fp16 tile ----
    auto load_stage = [&](int chunk, int stage) {
        const float* a_base; int a_stride;
        const __half* b_base; int b_stride;
        int k0;
        if (chunk < NCHUNK_MAIN) {
            a_base = w + (size_t)m_base * IN_F;  a_stride = IN_F;
            b_base = xh;                         b_stride = IN_F;
            k0 = chunk * KBLK;
        } else {
            a_base = lB + (size_t)m_base * RANK; a_stride = RANK;
            b_base = t2h;                        b_stride = RANK;
            k0 = (chunk - NCHUNK_MAIN) * KBLK;
        }
        uint32_t s_w = sb + OFF_W32 + (uint32_t)stage * W32_STAGE_B;
        // W: 128 rows x 8 x 16B = 1024 ops / 256 thr = 4 each
#pragma unroll
        for (int i = 0; i < 4; ++i) {
            int idx = tid + i * 256;
            int row = idx >> 3, c = idx & 7;
            cp16(s_w + (uint32_t)(row * P32 + c * 4) * 4,
                 a_base + (size_t)row * a_stride + k0 + c * 4);
        }
        // Xh: 64 rows x 4 x 16B = 256 ops = 1 each
        uint32_t s_x = sb + OFF_XH + (uint32_t)stage * XH_STAGE_B;
        {
            int row = tid >> 2, seg = tid & 3;
            cp16(s_x + (uint32_t)(row * PH + seg * 8) * 2,
                 b_base + (size_t)row * b_stride + k0 + seg * 8);
        }
    };

    // ---- prologue ----
#pragma unroll
    for (int s = 0; s < STAGES - 1; ++s) {
        load_stage(s, s);
        CP_COMMIT();
    }

    float d[2][4][4];
#pragma unroll
    for (int mi = 0; mi < 2; ++mi)
#pragma unroll
        for (int ni = 0; ni < 4; ++ni)
#pragma unroll
            for (int r = 0; r < 4; ++r) d[mi][ni][r] = 0.f;

    const int cvt_row = tid >> 1;
    const int cvt_c   = tid & 1;

    // ---- mainloop ----
    for (int it = 0; it < NCHUNK_TOT; ++it) {
        const int s = it & (STAGES - 1);
        CP_WAIT2();
        __syncthreads();   // stage s arrived; prior iter's LDSM done before Wh overwrite

        // convert W32[s] -> Wh (fp16), 16 floats per thread
        {
            const float* srcp = smem_f + s * W32_STAGE_F + cvt_row * P32 + cvt_c * 16;
            float4 v0 = ((const float4*)srcp)[0];
            float4 v1 = ((const float4*)srcp)[1];
            float4 v2 = ((const float4*)srcp)[2];
            float4 v3 = ((const float4*)srcp)[3];
            uint4 p0, p1;
            p0.x = h2u(__floats2half2_rn(v0.x, v0.y));
            p0.y = h2u(__floats2half2_rn(v0.z, v0.w));
            p0.z = h2u(__floats2half2_rn(v1.x, v1.y));
            p0.w = h2u(__floats2half2_rn(v1.z, v1.w));
            p1.x = h2u(__floats2half2_rn(v2.x, v2.y));
            p1.y = h2u(__floats2half2_rn(v2.z, v2.w));
            p1.z = h2u(__floats2half2_rn(v3.x, v3.y));
            p1.w = h2u(__floats2half2_rn(v3.z, v3.w));
            __half* whp = (__half*)(smem_c + OFF_WH) + cvt_row * PH + cvt_c * 16;
            ((uint4*)whp)[0] = p0;
            ((uint4*)(whp + 8))[0] = p1;
        }

        // refill stage (it+3)
        {
            int nc = it + STAGES - 1;
            if (nc < NCHUNK_TOT) load_stage(nc, nc & (STAGES - 1));
            CP_COMMIT();
        }
        __syncthreads();   // Wh visible to all warps

        const uint32_t xb = sb + OFF_XH + (uint32_t)s * XH_STAGE_B;
#pragma unroll
        for (int kk = 0; kk < 2; ++kk) {
            const uint32_t k2 = kk * 32;   // 16 halfs = 32B
            uint32_t a0[4], a1[4], bq0[4], bq1[4];
            ldsm4(a0,  a_off0 + k2);
            ldsm4(a1,  a_off1 + k2);
            ldsm4(bq0, xb + b_off0 + k2);
            ldsm4(bq1, xb + b_off1 + k2);
            mma_f16(d[0][0], a0, bq0[0], bq0[1]);
            mma_f16(d[0][1], a0, bq0[2], bq0[3]);
            mma_f16(d[0][2], a0, bq1[0], bq1[1]);
            mma_f16(d[0][3], a0, bq1[2], bq1[3]);
            mma_f16(d[1][0], a1, bq0[0], bq0[1]);
            mma_f16(d[1][1], a1, bq0[2], bq0[3]);
            mma_f16(d[1][2], a1, bq1[0], bq1[1]);
            mma_f16(d[1][3], a1, bq1[2], bq1[3]);
        }
    }

    // ---- epilogue: D[m][n] -> out[n][m] ----
#pragma unroll
    for (int mi = 0; mi < 2; ++mi) {
#pragma unroll
        for (int ni = 0; ni < 4; ++ni) {
            int m = m_base + wm + mi * 16 + g;
            int n = wn + ni * 8 + 2 * t;
            out[(size_t)n * OUT_F + m]           = d[mi][ni][0];
            out[(size_t)(n + 1) * OUT_F + m]     = d[mi][ni][1];
            out[(size_t)n * OUT_F + m + 8]       = d[mi][ni][2];
            out[(size_t)(n + 1) * OUT_F + m + 8] = d[mi][ni][3];
        }
    }
}

// ---------------- host launch ----------------
extern "C" void kernel_launch(void* const* d_in, const int* in_sizes, int n_in,
                              void* d_out, int out_size) {
    const float* x  = (const float*)d_in[0];   // [64, 4096]
    const float* w  = (const float*)d_in[1];   // [16384, 4096]
    const float* lA = (const float*)d_in[2];   // [64, 4096]
    const float* lB = (const float*)d_in[3];   // [16384, 64]
    float* out = (float*)d_out;                // [64, 16384]

    void* xh_ptr = nullptr;
    void* t2_ptr = nullptr;
    cudaGetSymbolAddress(&xh_ptr, g_xh);
    cudaGetSymbolAddress(&t2_ptr, g_t2h);

    x2h_kernel<<<(NTOK * IN_F / 4) / 256, 256>>>((const float4*)x, (uint2*)xh_ptr);
    lora_t_kernel<<<64, 256>>>(x, lA, (__half*)t2_ptr);

    static int smem_set = 0;
    if (!smem_set) {
        cudaFuncSetAttribute(lora_main_kernel,
                             cudaFuncAttributeMaxDynamicSharedMemorySize, SMEM_BYTES);
        smem_set = 1;
    }
    lora_main_kernel<<<OUT_F / BLOCK_M, 256, SMEM_BYTES>>>(
        (const __half*)xh_ptr, w, lB, (const __half*)t2_ptr, out);
}